// round 3
// baseline (speedup 1.0000x reference)
#include <cuda_runtime.h>
#include <cuda_bf16.h>
#include <cstdint>

#define CC 256
#define HH 128
#define WW 128
#define HWSZ (HH*WW)
#define SP   68                    // stage pitch (floats) per channel row
#define XBP  72                    // xbw pitch (words) per c2 row
#define KEYP 72                    // key pitch (bf16)

// shared layout (float indices)
#define SM_STG  0                          // fp32 stage [256][68]      = 17408
#define SM_XBW  17408                      // bf16 pairs [128][72] words = 9216
#define SM_KEY  (SM_XBW + 128*XBP)         // 26624: [64][72] bf16      = 2304 floats
#define SM_KQS  (SM_KEY + (64*KEYP)/2)     // 28928: [2][64 pix][4 s]   = 512
#define SM_WBUF (SM_KQS + 512)             // 29440: [4 win][68]        = 272
#define SM_WSS  (SM_WBUF + 272)            // 29712: [4][64]            = 256
#define SMEM_FLOATS (SM_WSS + 256)         // 29968
#define SMEM_BYTES (SMEM_FLOATS*4)         // 119872

__device__ __forceinline__ unsigned pack_bf2(float lo, float hi) {
    __nv_bfloat162 h = __floats2bfloat162_rn(lo, hi);
    return *reinterpret_cast<unsigned*>(&h);
}

__global__ __launch_bounds__(512, 1) void frac_fused_kernel(
    const float* __restrict__ x,
    const float* __restrict__ w_key,
    const float* __restrict__ w_sim,
    float* __restrict__ out)
{
    extern __shared__ float S[];
    unsigned*      xbw  = (unsigned*)(S + SM_XBW);       // [c2=128][72] words (c_even,c_odd)
    __nv_bfloat16* key  = (__nv_bfloat16*)(S + SM_KEY);
    unsigned*      keyw = (unsigned*)(S + SM_KEY);       // [64][36] words
    float*         kqs2 = S + SM_KQS;                    // [2][64][4]
    float*         wbuf = S + SM_WBUF;
    float*         wss  = S + SM_WSS;
    unsigned*      wkst = (unsigned*)(S + SM_XBW);       // prologue only: [64][132] words

    const int tid  = threadIdx.x;
    const int wp   = tid >> 5;
    const int lane = tid & 31;
    const int gid  = lane >> 2;        // 0..7
    const int ctid = lane & 3;         // 0..3
    const int mtb  = (wp & 3) * 16;    // key-row tile base
    const int pixb = (wp >> 2) * 16;   // pixel tile base
    const int wh = blockIdx.x;         // 0..1
    const int hh = blockIdx.y;         // 0..31
    const int n  = blockIdx.z;         // 0..15

    const uint32_t sbase = (uint32_t)__cvta_generic_to_shared(S);
    const float* xbase = x + ((size_t)n*CC)*HWSZ + (size_t)(hh*4)*WW + wh*64;

    // ---- prefetch chunk 0 into stage ----
    {
        #pragma unroll
        for (int i = 0; i < 8; i++) {
            int id = i*512 + tid;                  // 0..4095 16B units
            int c = id >> 4, r = (id >> 2) & 3, u = id & 3;
            const float* g = xbase + (size_t)c*HWSZ + r*WW + u*4;
            uint32_t d = sbase + (uint32_t)((c*SP + r*16 + u*4) * 4);
            asm volatile("cp.async.ca.shared.global [%0], [%1], 16;" :: "r"(d), "l"(g));
        }
        asm volatile("cp.async.commit_group;");
    }

    // ---- stage w_key as bf16 pairs into xbw region (prologue only) ----
    for (int i = tid; i < 64*128; i += 512) {
        int k = i >> 7, c2 = i & 127;
        float2 v = *(const float2*)(w_key + k*256 + c2*2);
        wkst[k*132 + c2] = pack_bf2(v.x, v.y);
    }
    if (tid < 256) wss[tid] = w_sim[tid];
    __syncthreads();

    // ---- A fragments (w_key) persistent in registers ----
    unsigned a[16][4];
    #pragma unroll
    for (int kt = 0; kt < 16; kt++) {
        a[kt][0] = wkst[(mtb+gid)  *132 + kt*8 + ctid];
        a[kt][1] = wkst[(mtb+gid+8)*132 + kt*8 + ctid];
        a[kt][2] = wkst[(mtb+gid)  *132 + kt*8 + ctid + 4];
        a[kt][3] = wkst[(mtb+gid+8)*132 + kt*8 + ctid + 4];
    }

    for (int ch = 0; ch < 4; ch++) {
        asm volatile("cp.async.wait_group 0;");
        __syncthreads();                         // stage(ch) ready; xbw free

        // ---- convert stage -> bf16 c-interleaved xbw ----
        #pragma unroll
        for (int j = 0; j < 4; j++) {
            int id = j*512 + tid;                // 0..2047 : 128 c2 x 16 p4
            int c2 = id >> 4, p4 = id & 15;
            float4 fa = *(const float4*)(S + SM_STG + (2*c2  )*SP + 4*p4);
            float4 fb = *(const float4*)(S + SM_STG + (2*c2+1)*SP + 4*p4);
            uint4 wv;
            wv.x = pack_bf2(fa.x, fb.x);
            wv.y = pack_bf2(fa.y, fb.y);
            wv.z = pack_bf2(fa.z, fb.z);
            wv.w = pack_bf2(fa.w, fb.w);
            *(uint4*)(xbw + c2*XBP + 4*p4) = wv;
        }
        __syncthreads();                         // xbw ready; stage drained

        if (ch < 3) {                            // prefetch next chunk into stage
            const float* src = xbase + (ch+1)*16;
            #pragma unroll
            for (int i = 0; i < 8; i++) {
                int id = i*512 + tid;
                int c = id >> 4, r = (id >> 2) & 3, u = id & 3;
                const float* g = src + (size_t)c*HWSZ + r*WW + u*4;
                uint32_t d = sbase + (uint32_t)((c*SP + r*16 + u*4) * 4);
                asm volatile("cp.async.ca.shared.global [%0], [%1], 16;" :: "r"(d), "l"(g));
            }
            asm volatile("cp.async.commit_group;");
        }

        // ---- GEMM: key[64 x 64pix] = Wk * x ----
        float acc[2][4] = {{0.f,0.f,0.f,0.f},{0.f,0.f,0.f,0.f}};
        #pragma unroll
        for (int kt = 0; kt < 16; kt++) {
            const int b0row = (kt*8 + ctid)     * XBP;
            const int b1row = (kt*8 + ctid + 4) * XBP;
            #pragma unroll
            for (int nt = 0; nt < 2; nt++) {
                int pix = pixb + nt*8 + gid;
                unsigned b0 = xbw[b0row + pix];
                unsigned b1 = xbw[b1row + pix];
                asm volatile(
                    "mma.sync.aligned.m16n8k16.row.col.f32.bf16.bf16.f32 "
                    "{%0,%1,%2,%3}, {%4,%5,%6,%7}, {%8,%9}, {%0,%1,%2,%3};"
                    : "+f"(acc[nt][0]), "+f"(acc[nt][1]), "+f"(acc[nt][2]), "+f"(acc[nt][3])
                    : "r"(a[kt][0]), "r"(a[kt][1]), "r"(a[kt][2]), "r"(a[kt][3]),
                      "r"(b0), "r"(b1));
            }
        }
        // relu(key) -> smem bf16 [key][pix]
        #pragma unroll
        for (int nt = 0; nt < 2; nt++) {
            int pw = (pixb >> 1) + nt*4 + ctid;
            keyw[(mtb+gid)  *36 + pw] = pack_bf2(fmaxf(acc[nt][0],0.f), fmaxf(acc[nt][1],0.f));
            keyw[(mtb+gid+8)*36 + pw] = pack_bf2(fmaxf(acc[nt][2],0.f), fmaxf(acc[nt][3],0.f));
        }
        __syncthreads();

        // ---- kq partials: all 512 threads, k split in halves ----
        {
            int kh  = tid >> 8;            // 0/1
            int r   = tid & 255;
            int pix = r >> 2, s = r & 3;
            float kq = 0.f;
            #pragma unroll 8
            for (int k = kh*32; k < kh*32 + 32; k++)
                kq += wss[s*64 + k] * __bfloat162float(key[k*KEYP + pix]);
            kqs2[kh*256 + pix*4 + s] = kq;
        }
        __syncthreads();

        // ---- per-window softmax over 16 pixels (logits / 4) ----
        if (tid < 16) {
            int win = tid >> 2, s = tid & 3;
            float v[16], m = -1e30f;
            #pragma unroll
            for (int r0 = 0; r0 < 4; r0++)
                #pragma unroll
                for (int j = 0; j < 4; j++) {
                    int idx = (r0*16 + win*4 + j)*4 + s;
                    float t = (kqs2[idx] + kqs2[256 + idx]) * 0.25f;
                    v[r0*4+j] = t;
                    m = fmaxf(m, t);
                }
            float sum = 0.f;
            #pragma unroll
            for (int p = 0; p < 16; p++) { float e = __expf(v[p]-m); v[p] = e; sum += e; }
            float inv = 1.f / sum;
            #pragma unroll
            for (int p = 0; p < 16; p++) wbuf[win*68 + p*4 + s] = v[p]*inv;
        }
        __syncthreads();

        // ---- aggregation from GLOBAL x (L1-hit, exact fp32) ----
        {
            const int sp   = tid & 1;
            const int win  = (tid >> 1) & 3;
            const int crow = tid >> 3;          // 0..63
            float2 w2[16];
            #pragma unroll
            for (int p = 0; p < 16; p++)
                w2[p] = *(const float2*)(wbuf + win*68 + p*4 + 2*sp);
            const int ww = wh*16 + ch*4 + win;
            #pragma unroll
            for (int cg = 0; cg < 4; cg++) {
                int c = cg*64 + crow;
                const float* xc = xbase + (size_t)c*HWSZ + ch*16 + win*4;
                float o0 = 0.f, o1 = 0.f;
                #pragma unroll
                for (int r0 = 0; r0 < 4; r0++) {
                    float4 xv = *(const float4*)(xc + r0*WW);
                    o0 += xv.x*w2[r0*4+0].x + xv.y*w2[r0*4+1].x
                        + xv.z*w2[r0*4+2].x + xv.w*w2[r0*4+3].x;
                    o1 += xv.x*w2[r0*4+0].y + xv.y*w2[r0*4+1].y
                        + xv.z*w2[r0*4+2].y + xv.w*w2[r0*4+3].y;
                }
                float2* op = (float2*)(out + ((size_t)(n*CC + c)*64 + (2*hh+sp))*64 + 2*ww);
                *op = make_float2(o0, o1);
            }
        }
        __syncthreads();
    }
}

extern "C" void kernel_launch(void* const* d_in, const int* in_sizes, int n_in,
                              void* d_out, int out_size)
{
    (void)in_sizes; (void)n_in; (void)out_size;
    const float* x  = (const float*)d_in[0];
    const float* wk = (const float*)d_in[1];
    const float* ws = (const float*)d_in[2];
    float* out = (float*)d_out;

    cudaFuncSetAttribute(frac_fused_kernel,
                         cudaFuncAttributeMaxDynamicSharedMemorySize, SMEM_BYTES);
    frac_fused_kernel<<<dim3(2, 32, 16), 512, SMEM_BYTES>>>(x, wk, ws, out);
}

// round 4
// speedup vs baseline: 1.2048x; 1.2048x over previous
#include <cuda_runtime.h>
#include <cuda_bf16.h>
#include <cstdint>

#define CC 256
#define HH 128
#define WW 128
#define HWSZ (HH*WW)
#define WKP_H 264                  // wk pitch in bf16 (132 words)
#define XBP  72                    // xbw pitch in words per c2 row
#define KEYP 72                    // key pitch in bf16 (36 words)

// shared layout in 4-byte units
#define SM_WK   0                          // [64][132] words = 8448
#define SM_XBW  8448                       // [128][72] words = 9216  (aliased by key after GEMM)
#define SM_KQS  17664                      // [2][64][4] = 512
#define SM_WBUF 18176                      // [4][68] = 272
#define SM_WSS  18448                      // [4][64] = 256
#define SMEM_WORDS 18704
#define SMEM_BYTES (SMEM_WORDS*4)          // 74816

__device__ __forceinline__ unsigned pack_bf2(float lo, float hi) {
    __nv_bfloat162 h = __floats2bfloat162_rn(lo, hi);
    return *reinterpret_cast<unsigned*>(&h);
}

__global__ __launch_bounds__(512, 2) void frac_fused_kernel(
    const float* __restrict__ x,
    const float* __restrict__ w_key,
    const float* __restrict__ w_sim,
    float* __restrict__ out)
{
    extern __shared__ float S[];
    unsigned*      wkw  = (unsigned*)(S + SM_WK);        // [key][132] words
    unsigned*      xbw  = (unsigned*)(S + SM_XBW);       // [c2][72] words (c_even,c_odd)
    __nv_bfloat16* key  = (__nv_bfloat16*)(S + SM_XBW);  // alias: [64][72] bf16
    unsigned*      keyw = (unsigned*)(S + SM_XBW);       // alias: [64][36] words
    float*         kqs2 = S + SM_KQS;
    float*         wbuf = S + SM_WBUF;
    float*         wss  = S + SM_WSS;

    const int tid  = threadIdx.x;
    const int wp   = tid >> 5;
    const int lane = tid & 31;
    const int gid  = lane >> 2;        // 0..7
    const int ctid = lane & 3;         // 0..3
    const int mtb  = (wp & 3) * 16;    // key-row tile base (4 M-tiles)
    const int pixb = (wp >> 2) * 16;   // pixel tile base (4 pix-tiles of 16)
    const int wh = blockIdx.x;         // 0..1
    const int hh = blockIdx.y;         // 0..31
    const int n  = blockIdx.z;         // 0..15

    const float* xbase = x + ((size_t)n*CC)*HWSZ + (size_t)(hh*4)*WW + wh*64;

    // ---- prologue: w_key -> bf16 smem [key][k], w_sim -> smem ----
    for (int i = tid; i < 64*128; i += 512) {
        int k = i >> 7, c2 = i & 127;
        float2 v = *(const float2*)(w_key + k*256 + c2*2);
        wkw[k*132 + c2] = pack_bf2(v.x, v.y);
    }
    if (tid < 256) wss[tid] = w_sim[tid];
    // (ordered by the barrier after the first convert below)

    // per-lane ldmatrix address for A (row = key, 16B col-half)
    const uint32_t wk_sb = (uint32_t)__cvta_generic_to_shared(S + SM_WK);
    const uint32_t a_lane_addr = wk_sb
        + (uint32_t)(((mtb + (lane & 15)) * WKP_H + (lane >> 4) * 8) * 2);

    for (int ch = 0; ch < 4; ch++) {
        if (ch) __syncthreads();               // key/kqs/wbuf consumed; xbw free
        const float* xch = xbase + ch*16;

        // ---- LDG fp32 -> pack bf16 c-interleaved -> STS xbw ----
        #pragma unroll
        for (int j = 0; j < 4; j++) {
            int id = j*512 + tid;              // 0..2047 : 128 c2 x 16 p4
            int c2 = id >> 4, p4 = id & 15;
            int r = p4 >> 2, u = p4 & 3;
            const float* g = xch + (size_t)(2*c2)*HWSZ + r*WW + u*4;
            float4 fa = *(const float4*)g;
            float4 fb = *(const float4*)(g + HWSZ);
            uint4 wv;
            wv.x = pack_bf2(fa.x, fb.x);
            wv.y = pack_bf2(fa.y, fb.y);
            wv.z = pack_bf2(fa.z, fb.z);
            wv.w = pack_bf2(fa.w, fb.w);
            *(uint4*)(xbw + c2*XBP + p4*4) = wv;
        }
        __syncthreads();                       // xbw ready (also orders prologue wk)

        // ---- GEMM: key[64 x 64pix] = Wk * x ; warp tile M=16,N=16 ----
        float acc[2][4] = {{0.f,0.f,0.f,0.f},{0.f,0.f,0.f,0.f}};
        #pragma unroll
        for (int kt = 0; kt < 16; kt++) {
            unsigned a0, a1, a2, a3;
            asm volatile(
                "ldmatrix.sync.aligned.m8n8.x4.shared.b16 {%0,%1,%2,%3}, [%4];"
                : "=r"(a0), "=r"(a1), "=r"(a2), "=r"(a3)
                : "r"(a_lane_addr + (unsigned)(kt*32)));
            const int b0row = (kt*8 + ctid)     * XBP;
            const int b1row = (kt*8 + ctid + 4) * XBP;
            #pragma unroll
            for (int nt = 0; nt < 2; nt++) {
                int pix = pixb + nt*8 + gid;
                unsigned b0 = xbw[b0row + pix];
                unsigned b1 = xbw[b1row + pix];
                asm volatile(
                    "mma.sync.aligned.m16n8k16.row.col.f32.bf16.bf16.f32 "
                    "{%0,%1,%2,%3}, {%4,%5,%6,%7}, {%8,%9}, {%0,%1,%2,%3};"
                    : "+f"(acc[nt][0]), "+f"(acc[nt][1]), "+f"(acc[nt][2]), "+f"(acc[nt][3])
                    : "r"(a0), "r"(a1), "r"(a2), "r"(a3), "r"(b0), "r"(b1));
            }
        }
        __syncthreads();                       // all xbw reads done before key alias write

        // ---- relu(key) -> smem bf16 [key][pix] (aliases xbw) ----
        #pragma unroll
        for (int nt = 0; nt < 2; nt++) {
            int pw = (pixb >> 1) + nt*4 + ctid;
            keyw[(mtb+gid)  *36 + pw] = pack_bf2(fmaxf(acc[nt][0],0.f), fmaxf(acc[nt][1],0.f));
            keyw[(mtb+gid+8)*36 + pw] = pack_bf2(fmaxf(acc[nt][2],0.f), fmaxf(acc[nt][3],0.f));
        }
        __syncthreads();

        // ---- kq partials: 512 threads, k halves ----
        {
            int kh  = tid >> 8;
            int rr  = tid & 255;
            int pix = rr >> 2, s = rr & 3;
            float kq = 0.f;
            #pragma unroll 8
            for (int k = kh*32; k < kh*32 + 32; k++)
                kq += wss[s*64 + k] * __bfloat162float(key[k*KEYP + pix]);
            kqs2[kh*256 + pix*4 + s] = kq;
        }
        __syncthreads();

        // ---- per-window softmax over 16 pixels (logits / 4) ----
        if (tid < 16) {
            int win = tid >> 2, s = tid & 3;
            float v[16], m = -1e30f;
            #pragma unroll
            for (int r0 = 0; r0 < 4; r0++)
                #pragma unroll
                for (int j = 0; j < 4; j++) {
                    int idx = (r0*16 + win*4 + j)*4 + s;
                    float t = (kqs2[idx] + kqs2[256 + idx]) * 0.25f;
                    v[r0*4+j] = t;
                    m = fmaxf(m, t);
                }
            float sum = 0.f;
            #pragma unroll
            for (int p = 0; p < 16; p++) { float e = __expf(v[p]-m); v[p] = e; sum += e; }
            float inv = 1.f / sum;
            #pragma unroll
            for (int p = 0; p < 16; p++) wbuf[win*68 + p*4 + s] = v[p]*inv;
        }
        __syncthreads();

        // ---- aggregation from global x (L1/L2-hit, exact fp32) ----
        {
            const int sp   = tid & 1;
            const int win  = (tid >> 1) & 3;
            const int crow = tid >> 3;          // 0..63
            float2 w2[16];
            #pragma unroll
            for (int p = 0; p < 16; p++)
                w2[p] = *(const float2*)(wbuf + win*68 + p*4 + 2*sp);
            const int ww = wh*16 + ch*4 + win;
            #pragma unroll
            for (int cg = 0; cg < 4; cg++) {
                int c = cg*64 + crow;
                const float* xc = xbase + (size_t)c*HWSZ + ch*16 + win*4;
                float o0 = 0.f, o1 = 0.f;
                #pragma unroll
                for (int r0 = 0; r0 < 4; r0++) {
                    float4 xv = *(const float4*)(xc + r0*WW);
                    o0 += xv.x*w2[r0*4+0].x + xv.y*w2[r0*4+1].x
                        + xv.z*w2[r0*4+2].x + xv.w*w2[r0*4+3].x;
                    o1 += xv.x*w2[r0*4+0].y + xv.y*w2[r0*4+1].y
                        + xv.z*w2[r0*4+2].y + xv.w*w2[r0*4+3].y;
                }
                float2* op = (float2*)(out + ((size_t)(n*CC + c)*64 + (2*hh+sp))*64 + 2*ww);
                *op = make_float2(o0, o1);
            }
        }
    }
}

extern "C" void kernel_launch(void* const* d_in, const int* in_sizes, int n_in,
                              void* d_out, int out_size)
{
    (void)in_sizes; (void)n_in; (void)out_size;
    const float* x  = (const float*)d_in[0];
    const float* wk = (const float*)d_in[1];
    const float* ws = (const float*)d_in[2];
    float* out = (float*)d_out;

    cudaFuncSetAttribute(frac_fused_kernel,
                         cudaFuncAttributeMaxDynamicSharedMemorySize, SMEM_BYTES);
    frac_fused_kernel<<<dim3(2, 32, 16), 512, SMEM_BYTES>>>(x, wk, ws, out);
}

// round 5
// speedup vs baseline: 1.3221x; 1.0973x over previous
#include <cuda_runtime.h>
#include <cuda_bf16.h>
#include <cstdint>

#define CC 256
#define HH 128
#define WW 128
#define HWSZ (HH*WW)
#define WKP_H 264                  // wk pitch in bf16 (132 words)
#define XBP  72                    // xbw pitch in words per c2 row

// shared layout in 4-byte units
#define SM_WK   0                          // [64][132] words = 8448
#define SM_XBW  8448                       // [128][72] words = 9216
#define SM_KQS  17664                      // [4 grp][64 pix][4 s] = 1024
#define SM_WBUF 18688                      // [4 win][68] = 272
#define SMEM_WORDS 18960
#define SMEM_BYTES (SMEM_WORDS*4)          // 75840

__device__ __forceinline__ unsigned pack_bf2(float lo, float hi) {
    __nv_bfloat162 h = __floats2bfloat162_rn(lo, hi);
    return *reinterpret_cast<unsigned*>(&h);
}

__global__ __launch_bounds__(512, 2) void frac_fused_kernel(
    const float* __restrict__ x,
    const float* __restrict__ w_key,
    const float* __restrict__ w_sim,
    float* __restrict__ out)
{
    extern __shared__ float S[];
    unsigned* wkw  = (unsigned*)(S + SM_WK);        // [key][132] words
    unsigned* xbw  = (unsigned*)(S + SM_XBW);       // [c2][72] words (c_even,c_odd)
    float*    kqs  = S + SM_KQS;                    // [grp][pix][s]
    float*    wbuf = S + SM_WBUF;

    const int tid  = threadIdx.x;
    const int wp   = tid >> 5;
    const int lane = tid & 31;
    const int gid  = lane >> 2;        // 0..7
    const int ctid = lane & 3;         // 0..3
    const int mtb  = (wp & 3) * 16;    // key-row tile base
    const int pixb = (wp >> 2) * 16;   // pixel tile base
    const int grp  = wp & 3;           // mtb group id for kq partials
    const int wh = blockIdx.x;         // 0..1
    const int hh = blockIdx.y;         // 0..31
    const int n  = blockIdx.z;         // 0..15

    const float* xbase = x + ((size_t)n*CC)*HWSZ + (size_t)(hh*4)*WW + wh*64;

    // ---- prologue: w_key -> bf16 smem [key][k] ----
    for (int i = tid; i < 64*128; i += 512) {
        int k = i >> 7, c2 = i & 127;
        float2 v = *(const float2*)(w_key + k*256 + c2*2);
        wkw[k*132 + c2] = pack_bf2(v.x, v.y);
    }
    // w_sim rows for this lane's two key rows (constant across chunks)
    float ws0[4], ws1[4];
    #pragma unroll
    for (int s = 0; s < 4; s++) {
        ws0[s] = w_sim[s*64 + mtb + gid];
        ws1[s] = w_sim[s*64 + mtb + gid + 8];
    }

    // per-lane ldmatrix address for A (row = key, 16B col-half)
    const uint32_t wk_sb = (uint32_t)__cvta_generic_to_shared(S + SM_WK);
    const uint32_t a_lane_addr = wk_sb
        + (uint32_t)(((mtb + (lane & 15)) * WKP_H + (lane >> 4) * 8) * 2);

    for (int ch = 0; ch < 4; ch++) {
        const float* xch = xbase + ch*16;

        // ---- LDG fp32 -> pack bf16 c-interleaved -> STS xbw ----
        #pragma unroll
        for (int j = 0; j < 4; j++) {
            int id = j*512 + tid;              // 0..2047 : 128 c2 x 16 p4
            int c2 = id >> 4, p4 = id & 15;
            int r = p4 >> 2, u = p4 & 3;
            const float* g = xch + (size_t)(2*c2)*HWSZ + r*WW + u*4;
            float4 fa = *(const float4*)g;
            float4 fb = *(const float4*)(g + HWSZ);
            uint4 wv;
            wv.x = pack_bf2(fa.x, fb.x);
            wv.y = pack_bf2(fa.y, fb.y);
            wv.z = pack_bf2(fa.z, fb.z);
            wv.w = pack_bf2(fa.w, fb.w);
            *(uint4*)(xbw + c2*XBP + p4*4) = wv;
        }
        __syncthreads();                       // xbw ready (also orders prologue wk)

        // ---- GEMM: key[64 x 64pix] = Wk * x ; warp tile M=16,N=16 ----
        float acc[2][4] = {{0.f,0.f,0.f,0.f},{0.f,0.f,0.f,0.f}};
        #pragma unroll
        for (int kt = 0; kt < 16; kt++) {
            unsigned a0, a1, a2, a3;
            asm volatile(
                "ldmatrix.sync.aligned.m8n8.x4.shared.b16 {%0,%1,%2,%3}, [%4];"
                : "=r"(a0), "=r"(a1), "=r"(a2), "=r"(a3)
                : "r"(a_lane_addr + (unsigned)(kt*32)));
            const int b0row = (kt*8 + ctid)     * XBP;
            const int b1row = (kt*8 + ctid + 4) * XBP;
            #pragma unroll
            for (int nt = 0; nt < 2; nt++) {
                int pix = pixb + nt*8 + gid;
                unsigned b0 = xbw[b0row + pix];
                unsigned b1 = xbw[b1row + pix];
                asm volatile(
                    "mma.sync.aligned.m16n8k16.row.col.f32.bf16.bf16.f32 "
                    "{%0,%1,%2,%3}, {%4,%5,%6,%7}, {%8,%9}, {%0,%1,%2,%3};"
                    : "+f"(acc[nt][0]), "+f"(acc[nt][1]), "+f"(acc[nt][2]), "+f"(acc[nt][3])
                    : "r"(a0), "r"(a1), "r"(a2), "r"(a3), "r"(b0), "r"(b1));
            }
        }

        // ---- kq in epilogue: part[nt][u][s] over this lane's 2 key rows ----
        float part[2][2][4];
        #pragma unroll
        for (int nt = 0; nt < 2; nt++)
            #pragma unroll
            for (int u = 0; u < 2; u++) {
                float v0 = fmaxf(acc[nt][u],     0.f);   // row mtb+gid
                float v1 = fmaxf(acc[nt][2 + u], 0.f);   // row mtb+gid+8
                #pragma unroll
                for (int s = 0; s < 4; s++)
                    part[nt][u][s] = ws0[s]*v0 + ws1[s]*v1;
            }
        // reduce across the 8 gid lanes (lane bits 2,3,4)
        #pragma unroll
        for (int off = 4; off <= 16; off <<= 1)
            #pragma unroll
            for (int nt = 0; nt < 2; nt++)
                #pragma unroll
                for (int u = 0; u < 2; u++)
                    #pragma unroll
                    for (int s = 0; s < 4; s++)
                        part[nt][u][s] += __shfl_xor_sync(0xffffffffu, part[nt][u][s], off);
        // lanes 0..3 (gid==0) store per-group partials: kqs[grp][pix][0..3]
        if (gid == 0) {
            #pragma unroll
            for (int nt = 0; nt < 2; nt++)
                #pragma unroll
                for (int u = 0; u < 2; u++) {
                    int pix = pixb + nt*8 + 2*ctid + u;
                    *(float4*)(kqs + grp*256 + pix*4) = make_float4(
                        part[nt][u][0], part[nt][u][1], part[nt][u][2], part[nt][u][3]);
                }
        }
        __syncthreads();                       // kqs ready; xbw reads done

        // ---- per-window softmax over 16 pixels (sum 4 group partials, /4) ----
        if (tid < 16) {
            int win = tid >> 2, s = tid & 3;
            float v[16], m = -1e30f;
            #pragma unroll
            for (int r0 = 0; r0 < 4; r0++)
                #pragma unroll
                for (int j = 0; j < 4; j++) {
                    int pix = r0*16 + win*4 + j;
                    float t = kqs[pix*4 + s] + kqs[256 + pix*4 + s]
                            + kqs[512 + pix*4 + s] + kqs[768 + pix*4 + s];
                    t *= 0.25f;
                    v[r0*4+j] = t;
                    m = fmaxf(m, t);
                }
            float sum = 0.f;
            #pragma unroll
            for (int p = 0; p < 16; p++) { float e = __expf(v[p]-m); v[p] = e; sum += e; }
            float inv = 1.f / sum;
            #pragma unroll
            for (int p = 0; p < 16; p++) wbuf[win*68 + p*4 + s] = v[p]*inv;
        }
        __syncthreads();                       // wbuf ready; kqs reads done

        // ---- aggregation from global x (L1-hit, exact fp32) ----
        {
            const int sp   = tid & 1;
            const int win  = (tid >> 1) & 3;
            const int crow = tid >> 3;          // 0..63
            float2 w2[16];
            #pragma unroll
            for (int p = 0; p < 16; p++)
                w2[p] = *(const float2*)(wbuf + win*68 + p*4 + 2*sp);
            const int ww = wh*16 + ch*4 + win;
            #pragma unroll
            for (int cg = 0; cg < 4; cg++) {
                int c = cg*64 + crow;
                const float* xc = xbase + (size_t)c*HWSZ + ch*16 + win*4;
                float o0 = 0.f, o1 = 0.f;
                #pragma unroll
                for (int r0 = 0; r0 < 4; r0++) {
                    float4 xv = *(const float4*)(xc + r0*WW);
                    o0 += xv.x*w2[r0*4+0].x + xv.y*w2[r0*4+1].x
                        + xv.z*w2[r0*4+2].x + xv.w*w2[r0*4+3].x;
                    o1 += xv.x*w2[r0*4+0].y + xv.y*w2[r0*4+1].y
                        + xv.z*w2[r0*4+2].y + xv.w*w2[r0*4+3].y;
                }
                float2* op = (float2*)(out + ((size_t)(n*CC + c)*64 + (2*hh+sp))*64 + 2*ww);
                *op = make_float2(o0, o1);
            }
        }
        __syncthreads();                       // wbuf/kqs consumed; xbw free for next chunk
    }
}

extern "C" void kernel_launch(void* const* d_in, const int* in_sizes, int n_in,
                              void* d_out, int out_size)
{
    (void)in_sizes; (void)n_in; (void)out_size;
    const float* x  = (const float*)d_in[0];
    const float* wk = (const float*)d_in[1];
    const float* ws = (const float*)d_in[2];
    float* out = (float*)d_out;

    cudaFuncSetAttribute(frac_fused_kernel,
                         cudaFuncAttributeMaxDynamicSharedMemorySize, SMEM_BYTES);
    frac_fused_kernel<<<dim3(2, 32, 16), 512, SMEM_BYTES>>>(x, wk, ws, out);
}

// round 6
// speedup vs baseline: 1.7256x; 1.3052x over previous
#include <cuda_runtime.h>
#include <cuda_bf16.h>
#include <cstdint>

#define CC 256
#define HH 128
#define WW 128
#define HWSZ (HH*WW)
#define WKP_W 132                  // wk pitch in words (264 bf16)
#define XBP   264                  // xbw pitch in words per c2 row (256 pix + 8 pad)

// shared layout in 4-byte units
#define SM_WK   0                          // [64][132] words  = 8448
#define SM_XBW  8448                       // [32][264] words  = 8448
#define SM_KQS  16896                      // [4 grp][256 pix][4 s] = 4096
#define SM_WBUF 20992                      // [16 win][68] = 1088
#define SMEM_WORDS 22080
#define SMEM_BYTES (SMEM_WORDS*4)          // 88320

__device__ __forceinline__ unsigned pack_bf2(float lo, float hi) {
    __nv_bfloat162 h = __floats2bfloat162_rn(lo, hi);
    return *reinterpret_cast<unsigned*>(&h);
}

__global__ __launch_bounds__(512, 2) void frac_fused_kernel(
    const float* __restrict__ x,
    const float* __restrict__ w_key,
    const float* __restrict__ w_sim,
    float* __restrict__ out)
{
    extern __shared__ float S[];
    unsigned* wkw  = (unsigned*)(S + SM_WK);        // [key][132] words
    unsigned* xbw  = (unsigned*)(S + SM_XBW);       // [c2l][264] words (c_even,c_odd per pixel)
    float*    kqs  = S + SM_KQS;                    // [grp][pix][s]
    float*    wbuf = S + SM_WBUF;                   // [win][16p][4s] pitch 68

    const int tid  = threadIdx.x;
    const int wp   = tid >> 5;
    const int lane = tid & 31;
    const int gid  = lane >> 2;        // 0..7
    const int ctid = lane & 3;         // 0..3
    const int mtb  = (wp & 3) * 16;    // key-row tile base
    const int grp  = wp & 3;
    const int pixb = (wp >> 2) * 64;   // pixel tile base (4 groups of 64)
    const int wh = blockIdx.x;         // 0..1
    const int hh = blockIdx.y;         // 0..31
    const int n  = blockIdx.z;         // 0..15

    // CTA pixel origin: rows hh*4.., cols wh*64..
    const float* xpix = x + ((size_t)n*CC)*HWSZ + (size_t)(hh*4)*WW + wh*64;

    // ---- prologue: w_key -> bf16 smem [key][k] ----
    for (int i = tid; i < 64*128; i += 512) {
        int k = i >> 7, c2 = i & 127;
        float2 v = *(const float2*)(w_key + k*256 + c2*2);
        wkw[k*WKP_W + c2] = pack_bf2(v.x, v.y);
    }

    // per-lane ldmatrix address for A (row = key, 16B col-half)
    const uint32_t wk_sb = (uint32_t)__cvta_generic_to_shared(S + SM_WK);
    const uint32_t a_lane_addr = wk_sb
        + (uint32_t)(((mtb + (lane & 15)) * (WKP_W*2) + (lane >> 4) * 8) * 2);

    // ---- K-chunked GEMM: key[64 x 256pix], K accumulated over 4 channel chunks ----
    float acc[8][4];
    #pragma unroll
    for (int i = 0; i < 8; i++)
        #pragma unroll
        for (int j = 0; j < 4; j++) acc[i][j] = 0.f;

    for (int ch = 0; ch < 4; ch++) {
        if (ch) __syncthreads();               // previous chunk's B reads done

        // convert channels [64ch, 64ch+64) x all 256 pixels -> bf16 pairs
        #pragma unroll
        for (int j = 0; j < 4; j++) {
            int id  = j*512 + tid;             // 0..2047 : c2l(32) x p4(64)
            int c2l = id >> 6, p4 = id & 63;
            int r = p4 >> 4, w4 = p4 & 15;
            const float* g = xpix + (size_t)(64*ch + 2*c2l)*HWSZ + r*WW + w4*4;
            float4 fa = *(const float4*)g;
            float4 fb = *(const float4*)(g + HWSZ);
            uint4 wv;
            wv.x = pack_bf2(fa.x, fb.x);
            wv.y = pack_bf2(fa.y, fb.y);
            wv.z = pack_bf2(fa.z, fb.z);
            wv.w = pack_bf2(fa.w, fb.w);
            *(uint4*)(xbw + c2l*XBP + r*64 + w4*4) = wv;
        }
        __syncthreads();                       // xbw ready (also orders prologue wk)

        #pragma unroll
        for (int ktl = 0; ktl < 4; ktl++) {
            unsigned a0, a1, a2, a3;
            asm volatile(
                "ldmatrix.sync.aligned.m8n8.x4.shared.b16 {%0,%1,%2,%3}, [%4];"
                : "=r"(a0), "=r"(a1), "=r"(a2), "=r"(a3)
                : "r"(a_lane_addr + (unsigned)((ch*4 + ktl)*32)));
            const int b0row = (ktl*8 + ctid)     * XBP;
            const int b1row = (ktl*8 + ctid + 4) * XBP;
            #pragma unroll
            for (int nt = 0; nt < 8; nt++) {
                int pix = pixb + nt*8 + gid;
                unsigned b0 = xbw[b0row + pix];
                unsigned b1 = xbw[b1row + pix];
                asm volatile(
                    "mma.sync.aligned.m16n8k16.row.col.f32.bf16.bf16.f32 "
                    "{%0,%1,%2,%3}, {%4,%5,%6,%7}, {%8,%9}, {%0,%1,%2,%3};"
                    : "+f"(acc[nt][0]), "+f"(acc[nt][1]), "+f"(acc[nt][2]), "+f"(acc[nt][3])
                    : "r"(a0), "r"(a1), "r"(a2), "r"(a3), "r"(b0), "r"(b1));
            }
        }
    }

    // ---- epilogue kq: relu + w_sim contraction from accumulators (once) ----
    float ws0[4], ws1[4];
    #pragma unroll
    for (int s = 0; s < 4; s++) {
        ws0[s] = w_sim[s*64 + mtb + gid];
        ws1[s] = w_sim[s*64 + mtb + gid + 8];
    }
    #pragma unroll
    for (int nt = 0; nt < 8; nt++) {
        float part[2][4];
        #pragma unroll
        for (int u = 0; u < 2; u++) {
            float v0 = fmaxf(acc[nt][u],     0.f);   // row mtb+gid
            float v1 = fmaxf(acc[nt][2 + u], 0.f);   // row mtb+gid+8
            #pragma unroll
            for (int s = 0; s < 4; s++)
                part[u][s] = ws0[s]*v0 + ws1[s]*v1;
        }
        #pragma unroll
        for (int off = 4; off <= 16; off <<= 1)
            #pragma unroll
            for (int u = 0; u < 2; u++)
                #pragma unroll
                for (int s = 0; s < 4; s++)
                    part[u][s] += __shfl_xor_sync(0xffffffffu, part[u][s], off);
        if (gid == 0) {
            #pragma unroll
            for (int u = 0; u < 2; u++) {
                int pix = pixb + nt*8 + 2*ctid + u;
                *(float4*)(kqs + grp*1024 + pix*4) = make_float4(
                    part[u][0], part[u][1], part[u][2], part[u][3]);
            }
        }
    }
    __syncthreads();                           // kqs complete

    // ---- per-window softmax (16 windows x 4 s = 64 threads) ----
    if (tid < 64) {
        int win = tid >> 2, s = tid & 3;
        float v[16], m = -1e30f;
        #pragma unroll
        for (int r0 = 0; r0 < 4; r0++)
            #pragma unroll
            for (int j = 0; j < 4; j++) {
                int pix = r0*64 + win*4 + j;
                float t = kqs[pix*4 + s] + kqs[1024 + pix*4 + s]
                        + kqs[2048 + pix*4 + s] + kqs[3072 + pix*4 + s];
                t *= 0.25f;
                v[r0*4+j] = t;
                m = fmaxf(m, t);
            }
        float sum = 0.f;
        #pragma unroll
        for (int p = 0; p < 16; p++) { float e = __expf(v[p]-m); v[p] = e; sum += e; }
        float inv = 1.f / sum;
        #pragma unroll
        for (int p = 0; p < 16; p++) wbuf[win*68 + p*4 + s] = v[p]*inv;
    }
    __syncthreads();                           // wbuf ready

    // ---- aggregation: lane = (win,sp); warp strides channels ----
    {
        const int sp  = tid & 1;
        const int win = (tid >> 1) & 15;
        float2 w2[16];
        #pragma unroll
        for (int p = 0; p < 16; p++)
            w2[p] = *(const float2*)(wbuf + win*68 + p*4 + 2*sp);
        const int ww = wh*16 + win;
        const float* gw = xpix + win*4;
        #pragma unroll 4
        for (int it = 0; it < 16; it++) {
            int c = it*16 + wp;
            const float* xc = gw + (size_t)c*HWSZ;
            float o0 = 0.f, o1 = 0.f;
            #pragma unroll
            for (int r0 = 0; r0 < 4; r0++) {
                float4 xv = *(const float4*)(xc + r0*WW);
                o0 += xv.x*w2[r0*4+0].x + xv.y*w2[r0*4+1].x
                    + xv.z*w2[r0*4+2].x + xv.w*w2[r0*4+3].x;
                o1 += xv.x*w2[r0*4+0].y + xv.y*w2[r0*4+1].y
                    + xv.z*w2[r0*4+2].y + xv.w*w2[r0*4+3].y;
            }
            float2* op = (float2*)(out + ((size_t)(n*CC + c)*64 + (2*hh+sp))*64 + 2*ww);
            *op = make_float2(o0, o1);
        }
    }
}

extern "C" void kernel_launch(void* const* d_in, const int* in_sizes, int n_in,
                              void* d_out, int out_size)
{
    (void)in_sizes; (void)n_in; (void)out_size;
    const float* x  = (const float*)d_in[0];
    const float* wk = (const float*)d_in[1];
    const float* ws = (const float*)d_in[2];
    float* out = (float*)d_out;

    cudaFuncSetAttribute(frac_fused_kernel,
                         cudaFuncAttributeMaxDynamicSharedMemorySize, SMEM_BYTES);
    frac_fused_kernel<<<dim3(2, 32, 16), 512, SMEM_BYTES>>>(x, wk, ws, out);
}